// round 15
// baseline (speedup 1.0000x reference)
#include <cuda_runtime.h>
#include <cuda_fp16.h>
#include <math.h>
#include <stdint.h>

// ---------------- problem constants ----------------
#define BATCH    512
#define SEQT     25
#define CH       512
#define NWIN     5
#define POOLW    5
#define BS       2560          // BATCH * NWIN
#define NROWS    5120          // 2 * BS
#define NT       40            // 128-row tiles per dim
#define NBLK     820           // NT*(NT+1)/2 upper-triangular tiles
#define TM       128
#define TEMP_INV 10.0f
#define SHIFT    10.0f
#define NCHUNK   8             // 512 / 64
#define BUFSTRIDE 36864        // one buffer: A(128*144) + B(128*144)
#define DSMEM    (2 * BUFSTRIDE)   // 73728 B dynamic

// ---------------- device scratch ----------------
__device__ __align__(16) __half g_znh[NROWS * CH];  // normalized rows, fp16
__device__ float g_rowS[NROWS];     // sum_j exp(logit-SHIFT), j != i
__device__ float g_rowPos[NROWS];   // positive logit per row
__device__ unsigned int g_done;     // last-CTA ticket (reset each replay by pool)

static __device__ __forceinline__ uint32_t smem_u32(const void* p) {
    uint32_t r;
    asm("{ .reg .u64 t; cvta.to.shared.u64 t, %1; cvt.u32.u64 %0, t; }" : "=r"(r) : "l"(p));
    return r;
}

#define LDSM_X4(R, addr) \
    asm volatile("ldmatrix.sync.aligned.m8n8.x4.shared.b16 {%0,%1,%2,%3}, [%4];" \
                 : "=r"((R)[0]), "=r"((R)[1]), "=r"((R)[2]), "=r"((R)[3]) : "r"(addr))

// fp16 in, fp16 accumulate (32 acc regs)
#define MMA16816H(C, A, B0, B1) \
    asm volatile("mma.sync.aligned.m16n8k16.row.col.f16.f16.f16.f16 " \
                 "{%0,%1}, {%2,%3,%4,%5}, {%6,%7}, {%0,%1};" \
                 : "+r"((C)[0]), "+r"((C)[1]) \
                 : "r"((A)[0]), "r"((A)[1]), "r"((A)[2]), "r"((A)[3]), \
                   "r"(B0), "r"(B1))

#define CP_ASYNC16(dst, src) \
    asm volatile("cp.async.cg.shared.global [%0], [%1], 16;" :: "r"(dst), "l"(src))
#define CP_COMMIT()  asm volatile("cp.async.commit_group;" ::: "memory")
#define CP_WAIT0()   asm volatile("cp.async.wait_group 0;" ::: "memory")

// ---------------------------------------------------------------------------
// Kernel A: adaptive-avg-pool + L2 normalize -> fp16 rows. 2 rows per block.
// Also zeros row accumulators, ticket, output (must run every replay).
// ---------------------------------------------------------------------------
__global__ __launch_bounds__(256) void pool_norm_kernel(const float* __restrict__ zi,
                                                        const float* __restrict__ zj,
                                                        float* __restrict__ out) {
    int half = threadIdx.x >> 7;
    int t    = threadIdx.x & 127;
    int r    = blockIdx.x * 2 + half;
    if (t == 0) {
        g_rowS[r] = 0.0f;
        if (r == 0) { out[0] = 0.0f; g_done = 0u; }
    }
    const float* src = (r < BS) ? zi : zj;
    int rr = (r < BS) ? r : r - BS;
    int b  = rr / NWIN;
    int w  = rr % NWIN;
    const float* base = src + ((size_t)(b * SEQT + w * POOLW)) * CH;

    int c0 = t * 4;
    float4 acc = make_float4(0.f, 0.f, 0.f, 0.f);
#pragma unroll
    for (int tt = 0; tt < POOLW; tt++) {
        float4 v = *(const float4*)(base + (size_t)tt * CH + c0);
        acc.x += v.x; acc.y += v.y; acc.z += v.z; acc.w += v.w;
    }
    acc.x *= 0.2f; acc.y *= 0.2f; acc.z *= 0.2f; acc.w *= 0.2f;

    float ss = acc.x * acc.x + acc.y * acc.y + acc.z * acc.z + acc.w * acc.w;
#pragma unroll
    for (int o = 16; o > 0; o >>= 1) ss += __shfl_xor_sync(0xffffffffu, ss, o);

    __shared__ float wsum[8];
    if ((threadIdx.x & 31) == 0) wsum[threadIdx.x >> 5] = ss;
    __syncthreads();
    float tot = wsum[half * 4] + wsum[half * 4 + 1] + wsum[half * 4 + 2] + wsum[half * 4 + 3];

    float inv = 1.0f / fmaxf(sqrtf(tot), 1e-8f);
    __half2 p0 = __floats2half2_rn(acc.x * inv, acc.y * inv);
    __half2 p1 = __floats2half2_rn(acc.z * inv, acc.w * inv);
    __half* dst = g_znh + (size_t)r * CH + c0;
    *(__half2*)(dst)     = p0;
    *(__half2*)(dst + 2) = p1;
}

// ---------------------------------------------------------------------------
// Kernel B: fp16 HMMA Gram tiles (upper triangle, 820 CTAs).
// cp.async double-buffered K=64 chunks (73.7KB dynamic, one barrier/chunk)
// + FRAGMENT double-buffering inside the ks loop (LDSM latency hidden
// in-warp). 256 threads; warp (wr,wc): rows wr*32..+32, cols wc*64..+64.
// Fused exp/row+col epilogue + last-CTA finalize. Carveout=100 -> 2 CTAs/SM.
// ---------------------------------------------------------------------------
__global__ __launch_bounds__(256, 2) void simclr_hmma_kernel(float* __restrict__ out) {
    // decode linear block id -> (rt, ct), ct >= rt
    int bid = blockIdx.x;
    int rt = (int)(0.5f * (81.0f - sqrtf(81.0f * 81.0f - 8.0f * (float)bid)));
    while ((rt + 1) * NT - ((rt + 1) * rt) / 2 <= bid) rt++;
    while (rt * NT - (rt * (rt - 1)) / 2 > bid) rt--;
    int ct = rt + bid - (rt * NT - (rt * (rt - 1)) / 2);

    const bool diag = (ct == rt);
    const bool haspos = (ct == rt + 20);      // +BS = 20 tiles

    extern __shared__ __align__(16) char tiles[];   // [2][A 18432 | B 18432]
    __shared__ float rowsm[TM];
    __shared__ float colsm[TM];
    __shared__ int lastflag;

    int tid = threadIdx.x;
    int wid = tid >> 5, lid = tid & 31;
    int wr = wid & 3, wc = wid >> 2;
    int g = lid >> 2, t4 = lid & 3;

    if (tid < TM) { rowsm[tid] = 0.f; colsm[tid] = 0.f; }

    uint32_t acc[2][8][2];
#pragma unroll
    for (int mi = 0; mi < 2; mi++)
#pragma unroll
        for (int na = 0; na < 8; na++) { acc[mi][na][0] = 0u; acc[mi][na][1] = 0u; }

    const __half* Ag = g_znh + (size_t)rt * TM * CH;
    const __half* Bg = g_znh + (size_t)ct * TM * CH;
    uint32_t sbase = smem_u32(tiles);

    // cp.async slots: seg = tid + it*256 -> row = seg>>3, ch = seg&7
    int lrow0 = tid >> 3,           lch0 = tid & 7;
    int lrow1 = (tid + 256) >> 3,   lch1 = (tid + 256) & 7;
    int lrow2 = (tid + 512) >> 3,   lch2 = (tid + 512) & 7;
    int lrow3 = (tid + 768) >> 3,   lch3 = (tid + 768) & 7;

#define ISSUE_CHUNK(cc)                                                          \
    do {                                                                         \
        uint32_t d = sbase + (uint32_t)((cc) & 1) * BUFSTRIDE;                   \
        int k0 = (cc) * 64;                                                      \
        CP_ASYNC16(d + lrow0 * 144 + lch0 * 16, Ag + (size_t)lrow0 * CH + k0 + lch0 * 8); \
        CP_ASYNC16(d + lrow1 * 144 + lch1 * 16, Ag + (size_t)lrow1 * CH + k0 + lch1 * 8); \
        CP_ASYNC16(d + lrow2 * 144 + lch2 * 16, Ag + (size_t)lrow2 * CH + k0 + lch2 * 8); \
        CP_ASYNC16(d + lrow3 * 144 + lch3 * 16, Ag + (size_t)lrow3 * CH + k0 + lch3 * 8); \
        CP_ASYNC16(d + 18432 + lrow0 * 144 + lch0 * 16, Bg + (size_t)lrow0 * CH + k0 + lch0 * 8); \
        CP_ASYNC16(d + 18432 + lrow1 * 144 + lch1 * 16, Bg + (size_t)lrow1 * CH + k0 + lch1 * 8); \
        CP_ASYNC16(d + 18432 + lrow2 * 144 + lch2 * 16, Bg + (size_t)lrow2 * CH + k0 + lch2 * 8); \
        CP_ASYNC16(d + 18432 + lrow3 * 144 + lch3 * 16, Bg + (size_t)lrow3 * CH + k0 + lch3 * 8); \
        CP_COMMIT();                                                             \
    } while (0)

    // per-warp LDSM base offsets (byte offsets within a buffer, excl. kk)
    uint32_t aoff0 = (uint32_t)((wr * 32 + (lid & 15)) * 144 + (lid >> 4) * 16);
    uint32_t aoff1 = aoff0 + 16 * 144;
    uint32_t boff0 = (uint32_t)(18432 + (wc * 64 + (lid & 15)) * 144 + (lid >> 4) * 16);
    uint32_t boff1 = boff0 + 16 * 144;
    uint32_t boff2 = boff0 + 32 * 144;
    uint32_t boff3 = boff0 + 48 * 144;

    ISSUE_CHUNK(0);

    for (int c = 0; c < NCHUNK; c++) {
        CP_WAIT0();
        __syncthreads();                  // chunk c visible to every warp

        if (c + 1 < NCHUNK) ISSUE_CHUNK(c + 1);   // readers of that buf done an iter ago

        uint32_t base = sbase + (uint32_t)(c & 1) * BUFSTRIDE;

        // fragment double-buffering: load ks+1 frags while MMA-ing ks
        uint32_t fa[2][2][4], fb[2][4][4];
        LDSM_X4(fa[0][0], base + aoff0);
        LDSM_X4(fa[0][1], base + aoff1);
        LDSM_X4(fb[0][0], base + boff0);
        LDSM_X4(fb[0][1], base + boff1);
        LDSM_X4(fb[0][2], base + boff2);
        LDSM_X4(fb[0][3], base + boff3);

#pragma unroll
        for (int ks = 0; ks < 4; ks++) {
            int cur = ks & 1, nxt = cur ^ 1;
            if (ks < 3) {
                uint32_t ko = (uint32_t)((ks + 1) * 32);   // 16 halves = 32 bytes
                LDSM_X4(fa[nxt][0], base + aoff0 + ko);
                LDSM_X4(fa[nxt][1], base + aoff1 + ko);
                LDSM_X4(fb[nxt][0], base + boff0 + ko);
                LDSM_X4(fb[nxt][1], base + boff1 + ko);
                LDSM_X4(fb[nxt][2], base + boff2 + ko);
                LDSM_X4(fb[nxt][3], base + boff3 + ko);
            }
#pragma unroll
            for (int mi = 0; mi < 2; mi++)
#pragma unroll
                for (int na = 0; na < 8; na++)
                    MMA16816H(acc[mi][na], fa[cur][mi],
                              fb[cur][na >> 1][na & 1], fb[cur][na >> 1][2 + (na & 1)]);
        }
        __syncthreads();                  // all warps done reading chunk c
    }

    // ---- fused epilogue ----
    int gr0 = rt * TM, gc0 = ct * TM;
    float colacc[16];
#pragma unroll
    for (int q = 0; q < 16; q++) colacc[q] = 0.f;
    float rowpart[2][2] = {{0.f, 0.f}, {0.f, 0.f}};

#pragma unroll
    for (int mi = 0; mi < 2; mi++) {
#pragma unroll
        for (int na = 0; na < 8; na++) {
#pragma unroll
            for (int h = 0; h < 2; h++) {
                float2 pr = __half22float2(*(const __half2*)&acc[mi][na][h]);
#pragma unroll
                for (int e = 0; e < 2; e++) {
                    int rl = wr * 32 + mi * 16 + g + h * 8;
                    int cl = wc * 64 + na * 8 + t4 * 2 + e;
                    float sim = (e == 0) ? pr.x : pr.y;
                    float ev = __expf(sim * TEMP_INV - SHIFT);
                    if (diag && rl == cl) ev = 0.f;
                    if (haspos && rl == cl) {
                        float lg = sim * TEMP_INV;
                        g_rowPos[gr0 + rl] = lg;
                        g_rowPos[gr0 + rl + BS] = lg;
                    }
                    rowpart[mi][h] += ev;
                    colacc[na * 2 + e] += ev;
                }
            }
        }
    }

    // row sums: reduce over t4 lanes (xor 1, 2)
#pragma unroll
    for (int mi = 0; mi < 2; mi++)
#pragma unroll
        for (int h = 0; h < 2; h++) {
            float v = rowpart[mi][h];
            v += __shfl_xor_sync(0xffffffffu, v, 1);
            v += __shfl_xor_sync(0xffffffffu, v, 2);
            if (t4 == 0) atomicAdd(&rowsm[wr * 32 + mi * 16 + g + h * 8], v);
        }

    // col sums: reduce over g lanes (xor 4, 8, 16)
#pragma unroll
    for (int q = 0; q < 16; q++) {
        float v = colacc[q];
        v += __shfl_xor_sync(0xffffffffu, v, 4);
        v += __shfl_xor_sync(0xffffffffu, v, 8);
        v += __shfl_xor_sync(0xffffffffu, v, 16);
        if (g == 0) atomicAdd(&colsm[wc * 64 + (q >> 1) * 8 + t4 * 2 + (q & 1)], v);
    }
    __syncthreads();

    if (tid < TM) {
        atomicAdd(&g_rowS[gr0 + tid], rowsm[tid]);
        if (!diag) atomicAdd(&g_rowS[gc0 + tid], colsm[tid]);
    }

    // ---- last-CTA finalize ----
    __threadfence();
    __syncthreads();
    if (tid == 0) {
        unsigned int old = atomicAdd(&g_done, 1u);
        lastflag = (old == NBLK - 1) ? 1 : 0;
    }
    __syncthreads();
    if (lastflag) {
        __threadfence();
        float part = 0.f;
#pragma unroll
        for (int it = 0; it < NROWS / 256; it++) {
            int i = it * 256 + tid;
            part += SHIFT + __logf(g_rowS[i]) - g_rowPos[i];
        }
#pragma unroll
        for (int o = 16; o > 0; o >>= 1) part += __shfl_xor_sync(0xffffffffu, part, o);
        if (lid == 0) rowsm[wid] = part;
        __syncthreads();
        if (tid == 0) {
            float tot = 0.f;
#pragma unroll
            for (int w = 0; w < 8; w++) tot += rowsm[w];
            out[0] = tot / (float)NROWS;
        }
    }
}

// ---------------------------------------------------------------------------
extern "C" void kernel_launch(void* const* d_in, const int* in_sizes, int n_in,
                              void* d_out, int out_size) {
    const float* zi = (const float*)d_in[0];
    const float* zj = (const float*)d_in[1];
    float* out = (float*)d_out;

    cudaFuncSetAttribute(simclr_hmma_kernel,
                         cudaFuncAttributeMaxDynamicSharedMemorySize, DSMEM);
    cudaFuncSetAttribute(simclr_hmma_kernel,
                         cudaFuncAttributePreferredSharedMemoryCarveout, 100);

    pool_norm_kernel<<<NROWS / 2, 256>>>(zi, zj, out);
    simclr_hmma_kernel<<<NBLK, 256, DSMEM>>>(out);
}